// round 1
// baseline (speedup 1.0000x reference)
#include <cuda_runtime.h>
#include <math.h>
#include <math_constants.h>

#define D_DIM 128
#define MAXN  50048
#define EPS_F 1e-8f

// Scratch for the diag-scaled projection y = (x @ W^T) * sqrt(softplus(log_diag)+eps)
__device__ float g_xp[(size_t)MAXN * D_DIM];

// ---------------------------------------------------------------------------
// Kernel 1: projection GEMM, 128x128 block tile, 8x8 register micro-tile,
// K tiled by 32 (keeps static smem under 48KB). Epilogue folds sqrt(diag).
// ---------------------------------------------------------------------------
__global__ __launch_bounds__(256) void proj_kernel(
    const float* __restrict__ X, const float* __restrict__ W,
    const float* __restrict__ logd, int N)
{
    __shared__ float Xs[128 * 32];   // [r][k] row-major, 16KB
    __shared__ float Wt[32 * 132];   // [k][c] padded pitch, ~16.9KB
    __shared__ float scale[128];

    const int tid  = threadIdx.x;
    const int row0 = blockIdx.x * 128;

    if (tid < 128) {
        float ld = logd[tid];
        float sp = (ld > 20.f) ? ld : log1pf(expf(ld));
        scale[tid] = sqrtf(sp + EPS_F);
    }

    float acc[8][8];
#pragma unroll
    for (int i = 0; i < 8; i++)
#pragma unroll
        for (int j = 0; j < 8; j++) acc[i][j] = 0.f;

    const int tx = tid & 15;         // column group (8 cols)
    const int ty = tid >> 4;         // row group    (8 rows)

    const int lr = tid >> 3;         // 0..31 : row (X) / col (W) index for loads
    const int lk = (tid & 7) * 4;    // k offset within tile (float4)

    for (int kt = 0; kt < 4; kt++) {
        __syncthreads();
        // X tile: rows row0..row0+127, k in [kt*32, kt*32+32)
#pragma unroll
        for (int it = 0; it < 4; it++) {
            int r  = lr + it * 32;
            int gr = row0 + r;
            float4 xv = make_float4(0.f, 0.f, 0.f, 0.f);
            if (gr < N) xv = *(const float4*)(X + (size_t)gr * D_DIM + kt * 32 + lk);
            *(float4*)(Xs + r * 32 + lk) = xv;
        }
        // W tile transposed: Wt[k][c] = W[c][kt*32+k]
#pragma unroll
        for (int it = 0; it < 4; it++) {
            int c = lr + it * 32;
            float4 wv = *(const float4*)(W + (size_t)c * D_DIM + kt * 32 + lk);
            Wt[(lk + 0) * 132 + c] = wv.x;
            Wt[(lk + 1) * 132 + c] = wv.y;
            Wt[(lk + 2) * 132 + c] = wv.z;
            Wt[(lk + 3) * 132 + c] = wv.w;
        }
        __syncthreads();

#pragma unroll 8
        for (int k = 0; k < 32; k++) {
            float xr[8];
#pragma unroll
            for (int i = 0; i < 8; i++) xr[i] = Xs[(ty * 8 + i) * 32 + k];
            float4 w0 = *(const float4*)(Wt + k * 132 + tx * 8);
            float4 w1 = *(const float4*)(Wt + k * 132 + tx * 8 + 4);
            float wc[8] = {w0.x, w0.y, w0.z, w0.w, w1.x, w1.y, w1.z, w1.w};
#pragma unroll
            for (int i = 0; i < 8; i++)
#pragma unroll
                for (int j = 0; j < 8; j++)
                    acc[i][j] = fmaf(xr[i], wc[j], acc[i][j]);
        }
    }

    // Epilogue: scale by sqrt(diag) and store
#pragma unroll
    for (int i = 0; i < 8; i++) {
        int gr = row0 + ty * 8 + i;
        if (gr < N) {
#pragma unroll
            for (int j = 0; j < 8; j += 4) {
                float4 o;
                o.x = acc[i][j + 0] * scale[tx * 8 + j + 0];
                o.y = acc[i][j + 1] * scale[tx * 8 + j + 1];
                o.z = acc[i][j + 2] * scale[tx * 8 + j + 2];
                o.w = acc[i][j + 3] * scale[tx * 8 + j + 3];
                *(float4*)(g_xp + (size_t)gr * D_DIM + tx * 8 + j) = o;
            }
        }
    }
}

// ---------------------------------------------------------------------------
// Kernel 2: one warp per node. Gather 16 neighbor rows (512B each, L2-hot),
// Mahalanobis scores via warp reduction, stable top-k (lax.top_k semantics),
// softmax over the selected set, outputs in ascending-neighbor-index order.
// ---------------------------------------------------------------------------
__global__ __launch_bounds__(256) void edge_kernel(
    const int* __restrict__ eidx, const float* __restrict__ logt,
    float* __restrict__ out, int N, int deg, int topk)
{
    const int warp = blockIdx.x * (blockDim.x >> 5) + (threadIdx.x >> 5);
    const int lane = threadIdx.x & 31;
    if (warp >= N) return;
    const int i = warp;

    // column indices for this node's edges (edge_index[1] segment)
    const int* colp = eidx + (size_t)N * deg + (size_t)i * deg;
    int mycol = (lane < deg) ? colp[lane] : 0;

    // this node's projected row: 4 floats per lane
    float4 yi = *(const float4*)(g_xp + (size_t)i * D_DIM + lane * 4);

    // issue all 16 neighbor gathers up front (MLP=16)
    float4 v[16];
#pragma unroll
    for (int n = 0; n < 16; n++) {
        int c = __shfl_sync(0xffffffffu, mycol, n);
        v[n] = *(const float4*)(g_xp + (size_t)c * D_DIM + lane * 4);
    }

    const float temp = expf(logt[0]);

    float s = -CUDART_INF_F;   // lanes >= 16 stay at -inf
#pragma unroll
    for (int n = 0; n < 16; n++) {
        float dx = yi.x - v[n].x;
        float dy = yi.y - v[n].y;
        float dz = yi.z - v[n].z;
        float dw = yi.w - v[n].w;
        float p = dx * dx + dy * dy + dz * dz + dw * dw;
#pragma unroll
        for (int o = 16; o > 0; o >>= 1)
            p += __shfl_xor_sync(0xffffffffu, p, o);
        if (lane == n) s = -p / temp;
    }

    // stable rank: number of strictly-greater scores, ties broken by lower lane
    int rank = 0;
#pragma unroll
    for (int m = 0; m < 16; m++) {
        float sm = __shfl_sync(0xffffffffu, s, m);
        rank += (sm > s || (sm == s && m < lane)) ? 1 : 0;
    }
    bool sel = rank < topk;                 // lanes>=16: rank==16, never selected
    unsigned bal = __ballot_sync(0xffffffffu, sel);

    // softmax over the selected set (== renorm forward value)
    float smax = sel ? s : -CUDART_INF_F;
#pragma unroll
    for (int o = 16; o > 0; o >>= 1)
        smax = fmaxf(smax, __shfl_xor_sync(0xffffffffu, smax, o));
    float e = sel ? expf(s - smax) : 0.f;
    float esum = e;
#pragma unroll
    for (int o = 16; o > 0; o >>= 1)
        esum += __shfl_xor_sync(0xffffffffu, esum, o);

    if (sel) {
        float w = e / esum;                 // esum >= 1, reference clip is a no-op
        int k = __popc(bal & ((1u << lane) - 1u));   // ascending-index output slot
        size_t NT = (size_t)N * topk;
        size_t base = (size_t)i * topk + k;
        out[base]          = (float)i;       // pruned_edge_index[0]
        out[NT + base]     = (float)mycol;   // pruned_edge_index[1]
        out[2 * NT + base] = w;              // pruned_edge_weight
    }
}

// ---------------------------------------------------------------------------
extern "C" void kernel_launch(void* const* d_in, const int* in_sizes, int n_in,
                              void* d_out, int out_size)
{
    const float* x    = (const float*)d_in[0];
    const int*   eidx = (const int*)  d_in[1];
    const float* W    = (const float*)d_in[2];
    const float* logd = (const float*)d_in[3];
    const float* logt = (const float*)d_in[4];

    const int D   = 128;
    const int N   = in_sizes[0] / D;
    const int deg = in_sizes[1] / (2 * N);
    const int topk = out_size / (3 * N);   // out = [2*N*topk idx, N*topk weights]

    float* out = (float*)d_out;

    proj_kernel<<<(N + 127) / 128, 256>>>(x, W, logd, N);

    int warps_per_block = 256 / 32;
    int blocks = (N + warps_per_block - 1) / warps_per_block;
    edge_kernel<<<blocks, 256>>>(eidx, logt, out, N, deg, topk);
}

// round 2
// speedup vs baseline: 1.3948x; 1.3948x over previous
#include <cuda_runtime.h>
#include <math.h>
#include <math_constants.h>

#define D_DIM 128
#define MAXN  50048
#define EPS_F 1e-8f
#define FULL  0xffffffffu

// Scratch for the diag-scaled projection y = (x @ W^T) * sqrt(softplus(log_diag)+eps)
__device__ float g_xp[(size_t)MAXN * D_DIM];

// ---------------------------------------------------------------------------
// Kernel 1: projection GEMM, 128x128 block tile, 8x8 register micro-tile,
// K tiled by 32. Epilogue folds sqrt(diag).  (unchanged from R1)
// ---------------------------------------------------------------------------
__global__ __launch_bounds__(256) void proj_kernel(
    const float* __restrict__ X, const float* __restrict__ W,
    const float* __restrict__ logd, int N)
{
    __shared__ float Xs[128 * 32];
    __shared__ float Wt[32 * 132];
    __shared__ float scale[128];

    const int tid  = threadIdx.x;
    const int row0 = blockIdx.x * 128;

    if (tid < 128) {
        float ld = logd[tid];
        float sp = (ld > 20.f) ? ld : log1pf(expf(ld));
        scale[tid] = sqrtf(sp + EPS_F);
    }

    float acc[8][8];
#pragma unroll
    for (int i = 0; i < 8; i++)
#pragma unroll
        for (int j = 0; j < 8; j++) acc[i][j] = 0.f;

    const int tx = tid & 15;
    const int ty = tid >> 4;
    const int lr = tid >> 3;
    const int lk = (tid & 7) * 4;

    for (int kt = 0; kt < 4; kt++) {
        __syncthreads();
#pragma unroll
        for (int it = 0; it < 4; it++) {
            int r  = lr + it * 32;
            int gr = row0 + r;
            float4 xv = make_float4(0.f, 0.f, 0.f, 0.f);
            if (gr < N) xv = *(const float4*)(X + (size_t)gr * D_DIM + kt * 32 + lk);
            *(float4*)(Xs + r * 32 + lk) = xv;
        }
#pragma unroll
        for (int it = 0; it < 4; it++) {
            int c = lr + it * 32;
            float4 wv = *(const float4*)(W + (size_t)c * D_DIM + kt * 32 + lk);
            Wt[(lk + 0) * 132 + c] = wv.x;
            Wt[(lk + 1) * 132 + c] = wv.y;
            Wt[(lk + 2) * 132 + c] = wv.z;
            Wt[(lk + 3) * 132 + c] = wv.w;
        }
        __syncthreads();

#pragma unroll 8
        for (int k = 0; k < 32; k++) {
            float xr[8];
#pragma unroll
            for (int i = 0; i < 8; i++) xr[i] = Xs[(ty * 8 + i) * 32 + k];
            float4 w0 = *(const float4*)(Wt + k * 132 + tx * 8);
            float4 w1 = *(const float4*)(Wt + k * 132 + tx * 8 + 4);
            float wc[8] = {w0.x, w0.y, w0.z, w0.w, w1.x, w1.y, w1.z, w1.w};
#pragma unroll
            for (int i = 0; i < 8; i++)
#pragma unroll
                for (int j = 0; j < 8; j++)
                    acc[i][j] = fmaf(xr[i], wc[j], acc[i][j]);
        }
    }

#pragma unroll
    for (int i = 0; i < 8; i++) {
        int gr = row0 + ty * 8 + i;
        if (gr < N) {
#pragma unroll
            for (int j = 0; j < 8; j += 4) {
                float4 o;
                o.x = acc[i][j + 0] * scale[tx * 8 + j + 0];
                o.y = acc[i][j + 1] * scale[tx * 8 + j + 1];
                o.z = acc[i][j + 2] * scale[tx * 8 + j + 2];
                o.w = acc[i][j + 3] * scale[tx * 8 + j + 3];
                *(float4*)(g_xp + (size_t)gr * D_DIM + tx * 8 + j) = o;
            }
        }
    }
}

// ---------------------------------------------------------------------------
// Kernel 2: one warp per node. Gathers in 2 groups of 8 (reg pressure),
// scores via multi-value butterfly transpose-reduce (17 shfls total),
// stable top-k + softmax, outputs in ascending-neighbor-index order.
// ---------------------------------------------------------------------------
__global__ __launch_bounds__(256, 4) void edge_kernel(
    const int* __restrict__ eidx, const float* __restrict__ logt,
    float* __restrict__ out, int N, int deg, int topk)
{
    const int warp = blockIdx.x * (blockDim.x >> 5) + (threadIdx.x >> 5);
    const int lane = threadIdx.x & 31;
    if (warp >= N) return;
    const int i = warp;

    const int* colp = eidx + (size_t)N * deg + (size_t)i * deg;
    int mycol = (lane < 16) ? colp[lane] : 0;

    float4 yi = *(const float4*)(g_xp + (size_t)i * D_DIM + lane * 4);

    const float rtemp = expf(-logt[0]);   // 1/temp (exact for logT==0)

    // partial squared distances: p[n] = sum over this lane's 4 dims
    float p[16];
#pragma unroll
    for (int g = 0; g < 2; g++) {
        float4 v[8];
#pragma unroll
        for (int n = 0; n < 8; n++) {
            int c = __shfl_sync(FULL, mycol, g * 8 + n);
            v[n] = *(const float4*)(g_xp + (size_t)c * D_DIM + lane * 4);
        }
#pragma unroll
        for (int n = 0; n < 8; n++) {
            float dx = yi.x - v[n].x;
            float dy = yi.y - v[n].y;
            float dz = yi.z - v[n].z;
            float dw = yi.w - v[n].w;
            p[g * 8 + n] = dx * dx + dy * dy + dz * dz + dw * dw;
        }
    }

    // Butterfly transpose-reduce: 16 values x 32 lanes -> lane l holds the
    // full 128-dim sum for neighbor rev4(l&15).
    {
        const bool b0 = lane & 1;
#pragma unroll
        for (int k = 0; k < 8; k++) {
            float send = b0 ? p[k] : p[k + 8];
            float recv = __shfl_xor_sync(FULL, send, 1);
            p[k] = (b0 ? p[k + 8] : p[k]) + recv;
        }
        const bool b1 = lane & 2;
#pragma unroll
        for (int k = 0; k < 4; k++) {
            float send = b1 ? p[k] : p[k + 4];
            float recv = __shfl_xor_sync(FULL, send, 2);
            p[k] = (b1 ? p[k + 4] : p[k]) + recv;
        }
        const bool b2 = lane & 4;
#pragma unroll
        for (int k = 0; k < 2; k++) {
            float send = b2 ? p[k] : p[k + 2];
            float recv = __shfl_xor_sync(FULL, send, 4);
            p[k] = (b2 ? p[k + 2] : p[k]) + recv;
        }
        const bool b3 = lane & 8;
        {
            float send = b3 ? p[0] : p[1];
            float recv = __shfl_xor_sync(FULL, send, 8);
            p[0] = (b3 ? p[1] : p[0]) + recv;
        }
        p[0] += __shfl_xor_sync(FULL, p[0], 16);
    }

    // Redistribute: lane n (n<16) needs neighbor n's sum, held at lane rev4(n).
    const int l4  = lane & 15;
    const int rev = ((l4 & 1) << 3) | ((l4 & 2) << 1) | ((l4 & 4) >> 1) | ((l4 & 8) >> 3);
    float raw = __shfl_sync(FULL, p[0], rev);
    float s = (lane < 16) ? (-raw * rtemp) : -CUDART_INF_F;

    // stable rank (lax.top_k semantics: ties -> lower index)
    int rank = 0;
#pragma unroll
    for (int m = 0; m < 16; m++) {
        float sm = __shfl_sync(FULL, s, m);
        rank += (sm > s || (sm == s && m < lane)) ? 1 : 0;
    }
    bool sel = rank < topk;
    unsigned bal = __ballot_sync(FULL, sel);

    // softmax over selected set (lanes 0..15 only carry live values)
    float smax = sel ? s : -CUDART_INF_F;
#pragma unroll
    for (int o = 8; o > 0; o >>= 1)
        smax = fmaxf(smax, __shfl_xor_sync(FULL, smax, o));
    float e = sel ? expf(s - smax) : 0.f;
    float esum = e;
#pragma unroll
    for (int o = 8; o > 0; o >>= 1)
        esum += __shfl_xor_sync(FULL, esum, o);

    if (sel) {
        float w = e / esum;
        int k = __popc(bal & ((1u << lane) - 1u));
        size_t NT = (size_t)N * topk;
        size_t base = (size_t)i * topk + k;
        out[base]          = (float)i;
        out[NT + base]     = (float)mycol;
        out[2 * NT + base] = w;
    }
}

// ---------------------------------------------------------------------------
extern "C" void kernel_launch(void* const* d_in, const int* in_sizes, int n_in,
                              void* d_out, int out_size)
{
    const float* x    = (const float*)d_in[0];
    const int*   eidx = (const int*)  d_in[1];
    const float* W    = (const float*)d_in[2];
    const float* logd = (const float*)d_in[3];
    const float* logt = (const float*)d_in[4];

    const int D   = 128;
    const int N   = in_sizes[0] / D;
    const int deg = in_sizes[1] / (2 * N);
    const int topk = out_size / (3 * N);

    float* out = (float*)d_out;

    proj_kernel<<<(N + 127) / 128, 256>>>(x, W, logd, N);

    int warps_per_block = 256 / 32;
    int blocks = (N + warps_per_block - 1) / warps_per_block;
    edge_kernel<<<blocks, 256>>>(eidx, logt, out, N, deg, topk);
}